// round 13
// baseline (speedup 1.0000x reference)
#include <cuda_runtime.h>

// Problem constants
#define HWD 256
#define CH_STRIDE (HWD * HWD)   // 65536 floats per channel plane
#define HB 128                  // h-rows per CTA
#define THREADS 512

// Shared buffers:
//   bufA  [128][256]: Qs (phase 1) -> S/P (softmax, phase 3)
//   bufB  [64][260] : Kt chunks [64 dw][256 g] (phase 1) -> Vs chunks [64 g][256 w]
//   strip [128][64] : A-term strip for current w-chunk (fused from Kt-fill loads)
#define ST_A 256
#define ST_B 260
#define ST_S 64
#define BUFA_FLOATS (128 * ST_A)                 // 32768
#define BUFB_FLOATS (64 * ST_B)                  // 16640
#define STRIP_FLOATS (128 * ST_S)                // 8192
#define SMEM_FLOATS (BUFA_FLOATS + BUFB_FLOATS + STRIP_FLOATS)   // 57600
#define SMEM_BYTES  (SMEM_FLOATS * 4)                            // 230400

typedef unsigned long long u64;

__device__ __forceinline__ u64 pk2(float x, float y) {
    u64 r; asm("mov.b64 %0, {%1, %2};" : "=l"(r) : "f"(x), "f"(y)); return r;
}
__device__ __forceinline__ void upk2(u64 v, float &x, float &y) {
    asm("mov.b64 {%0, %1}, %2;" : "=f"(x), "=f"(y) : "l"(v));
}
// Packed dual-fp32 FMA: d = a * b + d. Only path to full fp32 rate on sm_103a.
__device__ __forceinline__ void fma2(u64 &d, u64 a, u64 b) {
    asm("fma.rn.f32x2 %0, %1, %2, %0;" : "+l"(d) : "l"(a), "l"(b));
}

__global__ void __launch_bounds__(THREADS, 1)
fused_conv_attn_kernel(const float* __restrict__ x1, const float* __restrict__ x2,
                       const float* __restrict__ Wq, const float* __restrict__ bq,
                       const float* __restrict__ Wk, const float* __restrict__ bk,
                       const float* __restrict__ Wv, const float* __restrict__ bv,
                       const float* __restrict__ Wa, const float* __restrict__ ba,
                       float* __restrict__ out)
{
    extern __shared__ float sm[];
    float* bufA  = sm;                               // Qs -> S/P
    float* bufB  = sm + BUFA_FLOATS;                 // Kt chunks -> Vs chunks
    float* strip = sm + BUFA_FLOATS + BUFB_FLOATS;   // A strip [128][64]

    const int o   = blockIdx.x;   // 0..31 output channel
    const int hb  = blockIdx.y;   // 0..1  h block
    const int b   = blockIdx.z;   // 0..31 batch
    const int tid = threadIdx.x;
    const int lane = tid & 31;
    const int warp = tid >> 5;    // warp owns rows 8*warp .. 8*warp+7
    const int c0   = 8 * lane;    // thread's 8 columns (distinct across lanes)

    const float* x1b = x1 + (size_t)b * 3 * CH_STRIDE;
    const float* x2b = x2 + (size_t)b * 3 * CH_STRIDE;
    const int h0g = hb * HB;

    // ---------------- Q fill: bufA[h][w] = Wq . x1[:,h,w] + bq (float4, coalesced)
    {
        const float w0 = Wq[o*3+0], w1 = Wq[o*3+1], w2 = Wq[o*3+2], bb = bq[o];
        const int wi = (tid & 63) * 4;
        const int hbase = (tid >> 6) * 16;
        #pragma unroll 4
        for (int k = 0; k < 16; ++k) {
            const int h = hbase + k;
            const float* p = x1b + (size_t)(h0g + h) * HWD + wi;
            float4 c0v = *(const float4*)(p);
            float4 c1v = *(const float4*)(p + CH_STRIDE);
            float4 c2v = *(const float4*)(p + 2 * CH_STRIDE);
            float4 r;
            r.x = bb + w0*c0v.x + w1*c1v.x + w2*c2v.x;
            r.y = bb + w0*c0v.y + w1*c1v.y + w2*c2v.y;
            r.z = bb + w0*c0v.z + w1*c1v.z + w2*c2v.z;
            r.w = bb + w0*c0v.w + w1*c1v.w + w2*c2v.w;
            *(float4*)&bufA[h * ST_A + wi] = r;
        }
    }

    // ---------------- Phase 1: S[128h][256g] in registers, 8h x 8g per thread.
    // Lanes cover 256 distinct g columns (no duplicated K reads); q preloaded
    // as one broadcast float4 per row per 4 dw (2 wf/dw amortized).
    u64 sacc[8][4];
    #pragma unroll
    for (int i = 0; i < 8; ++i)
        #pragma unroll
        for (int m = 0; m < 4; ++m) sacc[i][m] = 0ull;

    const u64 k256 = pk2(256.0f, 256.0f);

    for (int wt = 0; wt < 4; ++wt) {
        if (wt > 0) __syncthreads();   // previous GEMM+fold done reading bufB/strip

        // Kt fill + A strip: lanes along w (coalesced float2 LDG),
        // transposed STS.32 into bufB[dw][g].
        {
            const float k0w = Wk[o*3+0], k1w = Wk[o*3+1], k2w = Wk[o*3+2], bbk = bk[o];
            const float a0w = Wa[o*3+0], a1w = Wa[o*3+1], a2w = Wa[o*3+2], bba = ba[o];
            const int dw = 2 * lane;
            #pragma unroll 4
            for (int k = 0; k < 16; ++k) {
                const int g = warp * 16 + k;
                const float* p = x2b + (size_t)g * HWD + wt * 64 + dw;
                float2 c0v = *(const float2*)(p);
                float2 c1v = *(const float2*)(p + CH_STRIDE);
                float2 c2v = *(const float2*)(p + 2 * CH_STRIDE);
                bufB[dw * ST_B + g]       = bbk + k0w*c0v.x + k1w*c1v.x + k2w*c2v.x;
                bufB[(dw + 1) * ST_B + g] = bbk + k0w*c0v.y + k1w*c1v.y + k2w*c2v.y;
                const int hloc = g - h0g;
                if ((unsigned)hloc < 128u) {   // warp-uniform branch
                    float2 a;
                    a.x = bba + a0w*c0v.x + a1w*c1v.x + a2w*c2v.x;
                    a.y = bba + a0w*c0v.y + a1w*c1v.y + a2w*c2v.y;
                    *(float2*)&strip[hloc * ST_S + dw] = a;
                }
            }
        }
        __syncthreads();

        // GEMM over this w chunk: dw blocked by 4, q preloaded as float4/row.
        const int wbase = wt * 64;
        const float* qrow0 = &bufA[(warp * 8) * ST_A + wbase];
        #pragma unroll 1
        for (int dw4 = 0; dw4 < 64; dw4 += 4) {
            float4 qv[8];
            #pragma unroll
            for (int i = 0; i < 8; ++i)
                qv[i] = *(const float4*)(qrow0 + i * ST_A + dw4);
            #pragma unroll
            for (int u = 0; u < 4; ++u) {
                const float* kr = &bufB[(dw4 + u) * ST_B + c0];
                ulonglong2 Ka = *(const ulonglong2*)(kr);
                ulonglong2 Kb = *(const ulonglong2*)(kr + 4);
                #pragma unroll
                for (int i = 0; i < 8; ++i) {
                    const float q = (&qv[i].x)[u];   // compile-time reg select
                    u64 qq = pk2(q, q);
                    fma2(sacc[i][0], qq, Ka.x); fma2(sacc[i][1], qq, Ka.y);
                    fma2(sacc[i][2], qq, Kb.x); fma2(sacc[i][3], qq, Kb.y);
                }
            }
        }

        // Fold A strip: thread's cols c0..c0+7 lie in chunk wt iff lane>>3 == wt.
        // sacc += 256*A (x256 here, x(1/256) in epilogue: both exact).
        if ((lane >> 3) == wt) {
            const int dwc = 8 * (lane & 7);
            #pragma unroll
            for (int i = 0; i < 8; ++i) {
                const float* sp = &strip[(warp * 8 + i) * ST_S + dwc];
                float4 a0 = *(const float4*)(sp);
                float4 a1 = *(const float4*)(sp + 4);
                fma2(sacc[i][0], pk2(a0.x, a0.y), k256);
                fma2(sacc[i][1], pk2(a0.z, a0.w), k256);
                fma2(sacc[i][2], pk2(a1.x, a1.y), k256);
                fma2(sacc[i][3], pk2(a1.z, a1.w), k256);
            }
        }
    }

    // ---------------- Epilogue: S = sacc/256 -> bufA rows 8*warp..+7 (warp-private)
    {
        const float inv = 1.0f / 256.0f;
        #pragma unroll
        for (int i = 0; i < 8; ++i) {
            float s0, s1, s2, s3, s4, s5, s6, s7;
            upk2(sacc[i][0], s0, s1); upk2(sacc[i][1], s2, s3);
            upk2(sacc[i][2], s4, s5); upk2(sacc[i][3], s6, s7);
            float* dst = &bufA[(warp * 8 + i) * ST_A + c0];
            *(float4*)(dst)     = make_float4(s0*inv, s1*inv, s2*inv, s3*inv);
            *(float4*)(dst + 4) = make_float4(s4*inv, s5*inv, s6*inv, s7*inv);
        }
    }
    __syncwarp();

    // ---------------- Softmax in place (warp per 8 rows; rows warp-private)
    {
        #pragma unroll 2
        for (int rr = 0; rr < 8; ++rr) {
            float* row = &bufA[(warp * 8 + rr) * ST_A];
            float4 v0 = *(float4*)&row[lane * 4];
            float4 v1 = *(float4*)&row[128 + lane * 4];
            float m = fmaxf(fmaxf(fmaxf(v0.x, v0.y), fmaxf(v0.z, v0.w)),
                            fmaxf(fmaxf(v1.x, v1.y), fmaxf(v1.z, v1.w)));
            #pragma unroll
            for (int off = 16; off; off >>= 1)
                m = fmaxf(m, __shfl_xor_sync(0xffffffffu, m, off));
            v0.x = __expf(v0.x - m); v0.y = __expf(v0.y - m);
            v0.z = __expf(v0.z - m); v0.w = __expf(v0.w - m);
            v1.x = __expf(v1.x - m); v1.y = __expf(v1.y - m);
            v1.z = __expf(v1.z - m); v1.w = __expf(v1.w - m);
            float s = v0.x + v0.y + v0.z + v0.w + v1.x + v1.y + v1.z + v1.w;
            #pragma unroll
            for (int off = 16; off; off >>= 1)
                s += __shfl_xor_sync(0xffffffffu, s, off);
            const float rinv = 1.0f / s;
            v0.x *= rinv; v0.y *= rinv; v0.z *= rinv; v0.w *= rinv;
            v1.x *= rinv; v1.y *= rinv; v1.z *= rinv; v1.w *= rinv;
            *(float4*)&row[lane * 4] = v0;
            *(float4*)&row[128 + lane * 4] = v1;
        }
    }
    __syncwarp();   // P rows warp-private; broadcast reads in phase 3

    // ---------------- Phase 3: O = P V, g tiled in 64-chunks; Vs in bufB.
    u64 oacc[8][4];
    #pragma unroll
    for (int i = 0; i < 8; ++i)
        #pragma unroll
        for (int m = 0; m < 4; ++m) oacc[i][m] = 0ull;

    for (int gt = 0; gt < 4; ++gt) {
        __syncthreads();   // phase-1 Kt reads done (gt=0) / previous Vs reads done

        // V fill: bufB[g][w] = Wv . x2[:, gt*64+g, w] + bv (float4, coalesced)
        {
            const float w0 = Wv[o*3+0], w1 = Wv[o*3+1], w2 = Wv[o*3+2], bb = bv[o];
            const int wi = (tid & 63) * 4;
            const int gbase = (tid >> 6) * 8;
            #pragma unroll 4
            for (int k = 0; k < 8; ++k) {
                const int g = gbase + k;
                const float* p = x2b + (size_t)(gt * 64 + g) * HWD + wi;
                float4 c0v = *(const float4*)(p);
                float4 c1v = *(const float4*)(p + CH_STRIDE);
                float4 c2v = *(const float4*)(p + 2 * CH_STRIDE);
                float4 r;
                r.x = bb + w0*c0v.x + w1*c1v.x + w2*c2v.x;
                r.y = bb + w0*c0v.y + w1*c1v.y + w2*c2v.y;
                r.z = bb + w0*c0v.z + w1*c1v.z + w2*c2v.z;
                r.w = bb + w0*c0v.w + w1*c1v.w + w2*c2v.w;
                *(float4*)&bufB[g * ST_B + wi] = r;
            }
        }
        __syncthreads();

        // GEMM: g blocked by 4, p preloaded as broadcast float4 per row.
        const float* prow0 = &bufA[(warp * 8) * ST_A + gt * 64];
        #pragma unroll 1
        for (int g4 = 0; g4 < 64; g4 += 4) {
            float4 pv[8];
            #pragma unroll
            for (int i = 0; i < 8; ++i)
                pv[i] = *(const float4*)(prow0 + i * ST_A + g4);
            #pragma unroll
            for (int u = 0; u < 4; ++u) {
                const float* vr = &bufB[(g4 + u) * ST_B + c0];
                ulonglong2 Va = *(const ulonglong2*)(vr);
                ulonglong2 Vb = *(const ulonglong2*)(vr + 4);
                #pragma unroll
                for (int i = 0; i < 8; ++i) {
                    const float p = (&pv[i].x)[u];   // compile-time reg select
                    u64 pp = pk2(p, p);
                    fma2(oacc[i][0], pp, Va.x); fma2(oacc[i][1], pp, Va.y);
                    fma2(oacc[i][2], pp, Vb.x); fma2(oacc[i][3], pp, Vb.y);
                }
            }
        }
    }

    // ---------------- Output: [b][o][h][w]; warp covers 1KB per row, coalesced
    float* ob = out + ((size_t)(b * 32 + o) * HWD + h0g) * HWD;
    #pragma unroll
    for (int i = 0; i < 8; ++i) {
        const int h = warp * 8 + i;
        float r0x, r0y, r0z, r0w, r1x, r1y, r1z, r1w;
        upk2(oacc[i][0], r0x, r0y); upk2(oacc[i][1], r0z, r0w);
        upk2(oacc[i][2], r1x, r1y); upk2(oacc[i][3], r1z, r1w);
        float* dst = &ob[(size_t)h * HWD + c0];
        *(float4*)(dst)     = make_float4(r0x, r0y, r0z, r0w);
        *(float4*)(dst + 4) = make_float4(r1x, r1y, r1z, r1w);
    }
}

extern "C" void kernel_launch(void* const* d_in, const int* in_sizes, int n_in,
                              void* d_out, int out_size)
{
    const float* x1 = (const float*)d_in[0];
    const float* x2 = (const float*)d_in[1];
    const float* Wq = (const float*)d_in[2];
    const float* bq = (const float*)d_in[3];
    const float* Wk = (const float*)d_in[4];
    const float* bk = (const float*)d_in[5];
    const float* Wv = (const float*)d_in[6];
    const float* bv = (const float*)d_in[7];
    const float* Wa = (const float*)d_in[8];
    const float* ba = (const float*)d_in[9];
    float* out = (float*)d_out;

    cudaFuncSetAttribute(fused_conv_attn_kernel,
                         cudaFuncAttributeMaxDynamicSharedMemorySize, SMEM_BYTES);

    dim3 grid(32, 2, 32);   // (o, h-block, b): consecutive CTAs share b -> x2[b] L2-resident
    fused_conv_attn_kernel<<<grid, THREADS, SMEM_BYTES>>>(
        x1, x2, Wq, bq, Wk, bk, Wv, bv, Wa, ba, out);
}

// round 14
// speedup vs baseline: 1.0386x; 1.0386x over previous
#include <cuda_runtime.h>

// Problem constants
#define HWD 256
#define CH_STRIDE (HWD * HWD)   // 65536 floats per channel plane
#define HB 128                  // h-rows per CTA
#define THREADS 512

// Shared buffers:
//   bufA  [128][256]: Qs (phase 1) -> S/P (softmax, phase 3)
//   bufB  [64][260] : Kt chunks [64 dw][256 g] (phase 1) -> Vs chunks [64 g][256 w]
//   strip [128][64] : A-term strip for current w-chunk (fused from Kt-fill loads)
#define ST_A 256
#define ST_B 260
#define ST_S 64
#define BUFA_FLOATS (128 * ST_A)                 // 32768
#define BUFB_FLOATS (64 * ST_B)                  // 16640
#define STRIP_FLOATS (128 * ST_S)                // 8192
#define SMEM_FLOATS (BUFA_FLOATS + BUFB_FLOATS + STRIP_FLOATS)   // 57600
#define SMEM_BYTES  (SMEM_FLOATS * 4)                            // 230400

typedef unsigned long long u64;

__device__ __forceinline__ u64 pk2(float x, float y) {
    u64 r; asm("mov.b64 %0, {%1, %2};" : "=l"(r) : "f"(x), "f"(y)); return r;
}
__device__ __forceinline__ void upk2(u64 v, float &x, float &y) {
    asm("mov.b64 {%0, %1}, %2;" : "=f"(x), "=f"(y) : "l"(v));
}
// Packed dual-fp32 FMA: d = a * b + d. Only path to full fp32 rate on sm_103a.
__device__ __forceinline__ void fma2(u64 &d, u64 a, u64 b) {
    asm("fma.rn.f32x2 %0, %1, %2, %0;" : "+l"(d) : "l"(a), "l"(b));
}

__global__ void __launch_bounds__(THREADS, 1)
fused_conv_attn_kernel(const float* __restrict__ x1, const float* __restrict__ x2,
                       const float* __restrict__ Wq, const float* __restrict__ bq,
                       const float* __restrict__ Wk, const float* __restrict__ bk,
                       const float* __restrict__ Wv, const float* __restrict__ bv,
                       const float* __restrict__ Wa, const float* __restrict__ ba,
                       float* __restrict__ out)
{
    extern __shared__ float sm[];
    float* bufA  = sm;                               // Qs -> S/P
    float* bufB  = sm + BUFA_FLOATS;                 // Kt chunks -> Vs chunks
    float* strip = sm + BUFA_FLOATS + BUFB_FLOATS;   // A strip [128][64]

    const int o   = blockIdx.x;   // 0..31 output channel
    const int hb  = blockIdx.y;   // 0..1  h block
    const int b   = blockIdx.z;   // 0..31 batch
    const int tid = threadIdx.x;
    const int lane = tid & 31;
    const int warp = tid >> 5;    // warp owns rows 8*warp .. 8*warp+7
    // Thread's column blocks: two contiguous-in-warp 4-col groups.
    // Block A covers g in [0,128), block B covers [128,256). Warp LDS of either
    // block = 32 lanes x 16B fully contiguous 512B -> 4 wavefronts, 0 conflicts.
    const int gA = 4 * lane;
    const int gB = 128 + 4 * lane;

    const float* x1b = x1 + (size_t)b * 3 * CH_STRIDE;
    const float* x2b = x2 + (size_t)b * 3 * CH_STRIDE;
    const int h0g = hb * HB;

    // ---------------- Q fill: bufA[h][w] = Wq . x1[:,h,w] + bq (float4, coalesced)
    {
        const float w0 = Wq[o*3+0], w1 = Wq[o*3+1], w2 = Wq[o*3+2], bb = bq[o];
        const int wi = (tid & 63) * 4;
        const int hbase = (tid >> 6) * 16;
        #pragma unroll 4
        for (int k = 0; k < 16; ++k) {
            const int h = hbase + k;
            const float* p = x1b + (size_t)(h0g + h) * HWD + wi;
            float4 c0v = *(const float4*)(p);
            float4 c1v = *(const float4*)(p + CH_STRIDE);
            float4 c2v = *(const float4*)(p + 2 * CH_STRIDE);
            float4 r;
            r.x = bb + w0*c0v.x + w1*c1v.x + w2*c2v.x;
            r.y = bb + w0*c0v.y + w1*c1v.y + w2*c2v.y;
            r.z = bb + w0*c0v.z + w1*c1v.z + w2*c2v.z;
            r.w = bb + w0*c0v.w + w1*c1v.w + w2*c2v.w;
            *(float4*)&bufA[h * ST_A + wi] = r;
        }
    }

    // ---------------- Phase 1: S[128h][256g] in registers, 8h x (4+4)g per thread.
    // sacc[i][0..1] = cols gA..gA+3, sacc[i][2..3] = cols gB..gB+3.
    u64 sacc[8][4];
    #pragma unroll
    for (int i = 0; i < 8; ++i)
        #pragma unroll
        for (int m = 0; m < 4; ++m) sacc[i][m] = 0ull;

    const u64 k256 = pk2(256.0f, 256.0f);

    for (int wt = 0; wt < 4; ++wt) {
        if (wt > 0) __syncthreads();   // previous GEMM+fold done reading bufB/strip

        // Kt fill + A strip: lanes along w (coalesced float2 LDG),
        // transposed STS.32 into bufB[dw][g].
        {
            const float k0w = Wk[o*3+0], k1w = Wk[o*3+1], k2w = Wk[o*3+2], bbk = bk[o];
            const float a0w = Wa[o*3+0], a1w = Wa[o*3+1], a2w = Wa[o*3+2], bba = ba[o];
            const int dw = 2 * lane;
            #pragma unroll 4
            for (int k = 0; k < 16; ++k) {
                const int g = warp * 16 + k;
                const float* p = x2b + (size_t)g * HWD + wt * 64 + dw;
                float2 c0v = *(const float2*)(p);
                float2 c1v = *(const float2*)(p + CH_STRIDE);
                float2 c2v = *(const float2*)(p + 2 * CH_STRIDE);
                bufB[dw * ST_B + g]       = bbk + k0w*c0v.x + k1w*c1v.x + k2w*c2v.x;
                bufB[(dw + 1) * ST_B + g] = bbk + k0w*c0v.y + k1w*c1v.y + k2w*c2v.y;
                const int hloc = g - h0g;
                if ((unsigned)hloc < 128u) {   // warp-uniform branch
                    float2 a;
                    a.x = bba + a0w*c0v.x + a1w*c1v.x + a2w*c2v.x;
                    a.y = bba + a0w*c0v.y + a1w*c1v.y + a2w*c2v.y;
                    *(float2*)&strip[hloc * ST_S + dw] = a;
                }
            }
        }
        __syncthreads();

        // GEMM over this w chunk: dw blocked by 4, q preloaded as broadcast
        // float4 per row; K loads contiguous 512B per warp (4 wf each).
        const int wbase = wt * 64;
        const float* qrow0 = &bufA[(warp * 8) * ST_A + wbase];
        #pragma unroll 1
        for (int dw4 = 0; dw4 < 64; dw4 += 4) {
            float4 qv[8];
            #pragma unroll
            for (int i = 0; i < 8; ++i)
                qv[i] = *(const float4*)(qrow0 + i * ST_A + dw4);
            #pragma unroll
            for (int u = 0; u < 4; ++u) {
                const float* kr = &bufB[(dw4 + u) * ST_B];
                ulonglong2 Ka = *(const ulonglong2*)(kr + gA);
                ulonglong2 Kb = *(const ulonglong2*)(kr + gB);
                #pragma unroll
                for (int i = 0; i < 8; ++i) {
                    const float q = (&qv[i].x)[u];   // compile-time reg select
                    u64 qq = pk2(q, q);
                    fma2(sacc[i][0], qq, Ka.x); fma2(sacc[i][1], qq, Ka.y);
                    fma2(sacc[i][2], qq, Kb.x); fma2(sacc[i][3], qq, Kb.y);
                }
            }
        }

        // Fold A strip: add 256*A for whichever of this thread's col blocks
        // lies inside chunk [wbase, wbase+64). (x256 here, x1/256 later: exact.)
        if (gA >= wbase && gA < wbase + 64) {
            const int dwc = gA - wbase;
            #pragma unroll
            for (int i = 0; i < 8; ++i) {
                float4 a = *(const float4*)&strip[(warp * 8 + i) * ST_S + dwc];
                fma2(sacc[i][0], pk2(a.x, a.y), k256);
                fma2(sacc[i][1], pk2(a.z, a.w), k256);
            }
        }
        if (gB >= wbase && gB < wbase + 64) {
            const int dwc = gB - wbase;
            #pragma unroll
            for (int i = 0; i < 8; ++i) {
                float4 a = *(const float4*)&strip[(warp * 8 + i) * ST_S + dwc];
                fma2(sacc[i][2], pk2(a.x, a.y), k256);
                fma2(sacc[i][3], pk2(a.z, a.w), k256);
            }
        }
    }

    // ---------------- Epilogue: S = sacc/256 -> bufA rows 8*warp..+7 (warp-private)
    {
        const float inv = 1.0f / 256.0f;
        #pragma unroll
        for (int i = 0; i < 8; ++i) {
            float s0, s1, s2, s3, s4, s5, s6, s7;
            upk2(sacc[i][0], s0, s1); upk2(sacc[i][1], s2, s3);
            upk2(sacc[i][2], s4, s5); upk2(sacc[i][3], s6, s7);
            float* dst = &bufA[(warp * 8 + i) * ST_A];
            *(float4*)(dst + gA) = make_float4(s0*inv, s1*inv, s2*inv, s3*inv);
            *(float4*)(dst + gB) = make_float4(s4*inv, s5*inv, s6*inv, s7*inv);
        }
    }
    __syncwarp();

    // ---------------- Softmax in place (warp per 8 rows; rows warp-private)
    {
        #pragma unroll 2
        for (int rr = 0; rr < 8; ++rr) {
            float* row = &bufA[(warp * 8 + rr) * ST_A];
            float4 v0 = *(float4*)&row[lane * 4];
            float4 v1 = *(float4*)&row[128 + lane * 4];
            float m = fmaxf(fmaxf(fmaxf(v0.x, v0.y), fmaxf(v0.z, v0.w)),
                            fmaxf(fmaxf(v1.x, v1.y), fmaxf(v1.z, v1.w)));
            #pragma unroll
            for (int off = 16; off; off >>= 1)
                m = fmaxf(m, __shfl_xor_sync(0xffffffffu, m, off));
            v0.x = __expf(v0.x - m); v0.y = __expf(v0.y - m);
            v0.z = __expf(v0.z - m); v0.w = __expf(v0.w - m);
            v1.x = __expf(v1.x - m); v1.y = __expf(v1.y - m);
            v1.z = __expf(v1.z - m); v1.w = __expf(v1.w - m);
            float s = v0.x + v0.y + v0.z + v0.w + v1.x + v1.y + v1.z + v1.w;
            #pragma unroll
            for (int off = 16; off; off >>= 1)
                s += __shfl_xor_sync(0xffffffffu, s, off);
            const float rinv = 1.0f / s;
            v0.x *= rinv; v0.y *= rinv; v0.z *= rinv; v0.w *= rinv;
            v1.x *= rinv; v1.y *= rinv; v1.z *= rinv; v1.w *= rinv;
            *(float4*)&row[lane * 4] = v0;
            *(float4*)&row[128 + lane * 4] = v1;
        }
    }
    __syncwarp();   // P rows warp-private; broadcast reads in phase 3

    // ---------------- Phase 3: O = P V, g tiled in 64-chunks; Vs in bufB.
    // oacc[i][0..1] = out cols gA..gA+3, oacc[i][2..3] = cols gB..gB+3.
    u64 oacc[8][4];
    #pragma unroll
    for (int i = 0; i < 8; ++i)
        #pragma unroll
        for (int m = 0; m < 4; ++m) oacc[i][m] = 0ull;

    for (int gt = 0; gt < 4; ++gt) {
        __syncthreads();   // phase-1 Kt reads done (gt=0) / previous Vs reads done

        // V fill: bufB[g][w] = Wv . x2[:, gt*64+g, w] + bv (float4, coalesced)
        {
            const float w0 = Wv[o*3+0], w1 = Wv[o*3+1], w2 = Wv[o*3+2], bb = bv[o];
            const int wi = (tid & 63) * 4;
            const int gbase = (tid >> 6) * 8;
            #pragma unroll 4
            for (int k = 0; k < 8; ++k) {
                const int g = gbase + k;
                const float* p = x2b + (size_t)(gt * 64 + g) * HWD + wi;
                float4 c0v = *(const float4*)(p);
                float4 c1v = *(const float4*)(p + CH_STRIDE);
                float4 c2v = *(const float4*)(p + 2 * CH_STRIDE);
                float4 r;
                r.x = bb + w0*c0v.x + w1*c1v.x + w2*c2v.x;
                r.y = bb + w0*c0v.y + w1*c1v.y + w2*c2v.y;
                r.z = bb + w0*c0v.z + w1*c1v.z + w2*c2v.z;
                r.w = bb + w0*c0v.w + w1*c1v.w + w2*c2v.w;
                *(float4*)&bufB[g * ST_B + wi] = r;
            }
        }
        __syncthreads();

        // GEMM: g blocked by 4, p preloaded as broadcast float4 per row;
        // V loads contiguous 512B per warp.
        const float* prow0 = &bufA[(warp * 8) * ST_A + gt * 64];
        #pragma unroll 1
        for (int g4 = 0; g4 < 64; g4 += 4) {
            float4 pv[8];
            #pragma unroll
            for (int i = 0; i < 8; ++i)
                pv[i] = *(const float4*)(prow0 + i * ST_A + g4);
            #pragma unroll
            for (int u = 0; u < 4; ++u) {
                const float* vr = &bufB[(g4 + u) * ST_B];
                ulonglong2 Va = *(const ulonglong2*)(vr + gA);
                ulonglong2 Vb = *(const ulonglong2*)(vr + gB);
                #pragma unroll
                for (int i = 0; i < 8; ++i) {
                    const float p = (&pv[i].x)[u];   // compile-time reg select
                    u64 pp = pk2(p, p);
                    fma2(oacc[i][0], pp, Va.x); fma2(oacc[i][1], pp, Va.y);
                    fma2(oacc[i][2], pp, Vb.x); fma2(oacc[i][3], pp, Vb.y);
                }
            }
        }
    }

    // ---------------- Output: [b][o][h][w]; two contiguous 512B runs per warp row
    float* ob = out + ((size_t)(b * 32 + o) * HWD + h0g) * HWD;
    #pragma unroll
    for (int i = 0; i < 8; ++i) {
        const int h = warp * 8 + i;
        float s0, s1, s2, s3, s4, s5, s6, s7;
        upk2(oacc[i][0], s0, s1); upk2(oacc[i][1], s2, s3);
        upk2(oacc[i][2], s4, s5); upk2(oacc[i][3], s6, s7);
        float* dst = &ob[(size_t)h * HWD];
        *(float4*)(dst + gA) = make_float4(s0, s1, s2, s3);
        *(float4*)(dst + gB) = make_float4(s4, s5, s6, s7);
    }
}

extern "C" void kernel_launch(void* const* d_in, const int* in_sizes, int n_in,
                              void* d_out, int out_size)
{
    const float* x1 = (const float*)d_in[0];
    const float* x2 = (const float*)d_in[1];
    const float* Wq = (const float*)d_in[2];
    const float* bq = (const float*)d_in[3];
    const float* Wk = (const float*)d_in[4];
    const float* bk = (const float*)d_in[5];
    const float* Wv = (const float*)d_in[6];
    const float* bv = (const float*)d_in[7];
    const float* Wa = (const float*)d_in[8];
    const float* ba = (const float*)d_in[9];
    float* out = (float*)d_out;

    cudaFuncSetAttribute(fused_conv_attn_kernel,
                         cudaFuncAttributeMaxDynamicSharedMemorySize, SMEM_BYTES);

    dim3 grid(32, 2, 32);   // (o, h-block, b): consecutive CTAs share b -> x2[b] L2-resident
    fused_conv_attn_kernel<<<grid, THREADS, SMEM_BYTES>>>(
        x1, x2, Wq, bq, Wk, bk, Wv, bv, Wa, ba, out);
}

// round 15
// speedup vs baseline: 1.1519x; 1.1091x over previous
#include <cuda_runtime.h>

// Problem constants
#define HWD 256
#define CH_STRIDE (HWD * HWD)   // 65536 floats per channel plane
#define HB 128                  // h-rows per CTA
#define THREADS 512

// Shared buffers:
//   bufA    [128][256] : Qs (phase 1) -> S/P (softmax, phase 3)
//   bufB[2] [32][260]  : double-buffered K-chunks (phase 1) / V-chunks (phase 3);
//                        next chunk is filled DURING the current chunk's GEMM.
#define ST_A 256
#define ST_B 260
#define BUFA_FLOATS (128 * ST_A)                  // 32768
#define BUFB_FLOATS (32 * ST_B)                   // 8320 per buffer
#define SMEM_FLOATS (BUFA_FLOATS + 2 * BUFB_FLOATS)   // 49408
#define SMEM_BYTES  (SMEM_FLOATS * 4)                 // 197632

typedef unsigned long long u64;

__device__ __forceinline__ u64 pk2(float x, float y) {
    u64 r; asm("mov.b64 %0, {%1, %2};" : "=l"(r) : "f"(x), "f"(y)); return r;
}
__device__ __forceinline__ void upk2(u64 v, float &x, float &y) {
    asm("mov.b64 {%0, %1}, %2;" : "=f"(x), "=f"(y) : "l"(v));
}
// Packed dual-fp32 FMA: d = a * b + d. Only path to full fp32 rate on sm_103a.
__device__ __forceinline__ void fma2(u64 &d, u64 a, u64 b) {
    asm("fma.rn.f32x2 %0, %1, %2, %0;" : "+l"(d) : "l"(a), "l"(b));
}

__global__ void __launch_bounds__(THREADS, 1)
fused_conv_attn_kernel(const float* __restrict__ x1, const float* __restrict__ x2,
                       const float* __restrict__ Wq, const float* __restrict__ bq,
                       const float* __restrict__ Wk, const float* __restrict__ bk,
                       const float* __restrict__ Wv, const float* __restrict__ bv,
                       const float* __restrict__ Wa, const float* __restrict__ ba,
                       float* __restrict__ out)
{
    extern __shared__ float sm[];
    float* bufA = sm;                    // Qs -> S/P
    float* bufB = sm + BUFA_FLOATS;      // two [32][260] chunk buffers

    const int o   = blockIdx.x;   // 0..31 output channel
    const int hb  = blockIdx.y;   // 0..1  h block
    const int b   = blockIdx.z;   // 0..31 batch
    const int tid = threadIdx.x;
    const int lane = tid & 31;
    const int warpq = tid >> 5;   // warp id (softmax rows / fill g-groups)
    const int tx  = tid & 15;     // 16 column groups (4 cols each, +64m)
    const int ty  = tid >> 4;     // 32 row groups (4 rows each)

    const float* x1b = x1 + (size_t)b * 3 * CH_STRIDE;
    const float* x2b = x2 + (size_t)b * 3 * CH_STRIDE;
    const int h0g = hb * HB;

    // Projection weights needed inside the pipelined loops (hoisted).
    const float k0w = Wk[o*3+0], k1w = Wk[o*3+1], k2w = Wk[o*3+2], bbk = bk[o];
    const float v0w = Wv[o*3+0], v1w = Wv[o*3+1], v2w = Wv[o*3+2], bbv = bv[o];

    // V-fill thread mapping (used in prefill + phase 3)
    const int wiv = (tid & 63) * 4;
    const int gv  = (tid >> 6) * 4;   // + sub -> local g row in [0,32)

    // ---------------- Q fill: bufA[h][w] = Wq . x1[:,h,w] + bq (float4, coalesced)
    {
        const float w0 = Wq[o*3+0], w1 = Wq[o*3+1], w2 = Wq[o*3+2], bb = bq[o];
        const int wi = (tid & 63) * 4;
        const int hbase = (tid >> 6) * 16;
        #pragma unroll 4
        for (int k = 0; k < 16; ++k) {
            const int h = hbase + k;
            const float* p = x1b + (size_t)(h0g + h) * HWD + wi;
            float4 c0v = *(const float4*)(p);
            float4 c1v = *(const float4*)(p + CH_STRIDE);
            float4 c2v = *(const float4*)(p + 2 * CH_STRIDE);
            float4 r;
            r.x = bb + w0*c0v.x + w1*c1v.x + w2*c2v.x;
            r.y = bb + w0*c0v.y + w1*c1v.y + w2*c2v.y;
            r.z = bb + w0*c0v.z + w1*c1v.z + w2*c2v.z;
            r.w = bb + w0*c0v.w + w1*c1v.w + w2*c2v.w;
            *(float4*)&bufA[h * ST_A + wi] = r;
        }
    }

    // ---------------- Prefill K chunk 0 into buffer 0 (transposed [dw][g]).
    // dw = lane (STS stride 260 floats -> 4-way conflict), g = warpq*16+k.
    {
        #pragma unroll 4
        for (int k = 0; k < 16; ++k) {
            const int g = warpq * 16 + k;
            const float* p = x2b + (size_t)g * HWD + lane;   // w0 = 0
            float c0 = p[0], c1 = p[CH_STRIDE], c2 = p[2*CH_STRIDE];
            bufB[lane * ST_B + g] = bbk + k0w*c0 + k1w*c1 + k2w*c2;
        }
    }
    __syncthreads();

    // ---------------- Phase 1: S[128h][256g] in registers (4h x 16g per thread),
    // 8 chunks of 32 dw, double-buffered: chunk wt+1 fills during chunk wt's GEMM.
    u64 sacc[4][8];
    #pragma unroll
    for (int i = 0; i < 4; ++i)
        #pragma unroll
        for (int m = 0; m < 8; ++m) sacc[i][m] = 0ull;

    for (int wt = 0; wt < 8; ++wt) {
        float* Bc = bufB + (wt & 1) * BUFB_FLOATS;
        float* Bn = bufB + ((wt & 1) ^ 1) * BUFB_FLOATS;
        const int w0 = wt * 32;

        for (int sub = 0; sub < 4; ++sub) {
            // ---- fill slice for the NEXT chunk (overlaps this GEMM) ----
            if (wt < 7) {
                const int w0n = w0 + 32;
                #pragma unroll
                for (int kk = 0; kk < 4; ++kk) {
                    const int g = warpq * 16 + sub * 4 + kk;
                    const float* p = x2b + (size_t)g * HWD + w0n + lane;
                    float c0 = p[0], c1 = p[CH_STRIDE], c2 = p[2*CH_STRIDE];
                    Bn[lane * ST_B + g] = bbk + k0w*c0 + k1w*c1 + k2w*c2;
                }
            } else {
                // prefill V chunk 0 (natural [g][w]) for phase 3, 1 row-slice/sub
                const int g = gv + sub;
                const float* p = x2b + (size_t)g * HWD + wiv;
                float4 c0v = *(const float4*)(p);
                float4 c1v = *(const float4*)(p + CH_STRIDE);
                float4 c2v = *(const float4*)(p + 2 * CH_STRIDE);
                float4 r;
                r.x = bbv + v0w*c0v.x + v1w*c1v.x + v2w*c2v.x;
                r.y = bbv + v0w*c0v.y + v1w*c1v.y + v2w*c2v.y;
                r.z = bbv + v0w*c0v.z + v1w*c1v.z + v2w*c2v.z;
                r.w = bbv + v0w*c0v.w + v1w*c1v.w + v2w*c2v.w;
                *(float4*)&Bn[g * ST_B + wiv] = r;
            }

            // ---- GEMM: 8 dw of current chunk ----
            #pragma unroll
            for (int dq = 0; dq < 2; ++dq) {
                const int dw4 = sub * 8 + dq * 4;
                float4 qv[4];
                #pragma unroll
                for (int i = 0; i < 4; ++i)
                    qv[i] = *(const float4*)&bufA[(4*ty + i) * ST_A + w0 + dw4];
                #pragma unroll
                for (int u = 0; u < 4; ++u) {
                    const float* kr = &Bc[(dw4 + u) * ST_B + 4 * tx];
                    ulonglong2 K0 = *(const ulonglong2*)(kr);
                    ulonglong2 K1 = *(const ulonglong2*)(kr + 64);
                    ulonglong2 K2 = *(const ulonglong2*)(kr + 128);
                    ulonglong2 K3 = *(const ulonglong2*)(kr + 192);
                    #pragma unroll
                    for (int i = 0; i < 4; ++i) {
                        const float q = (&qv[i].x)[u];
                        u64 qq = pk2(q, q);
                        fma2(sacc[i][0], qq, K0.x); fma2(sacc[i][1], qq, K0.y);
                        fma2(sacc[i][2], qq, K1.x); fma2(sacc[i][3], qq, K1.y);
                        fma2(sacc[i][4], qq, K2.x); fma2(sacc[i][5], qq, K2.y);
                        fma2(sacc[i][6], qq, K3.x); fma2(sacc[i][7], qq, K3.y);
                    }
                }
            }
        }
        __syncthreads();   // next chunk fully written; current fully read
    }

    // ---------------- Epilogue: S = sacc/256 + A-term (direct x2 read) -> bufA.
    // Rows warp-private (thread wrote/read only its own 4 rows).
    {
        const float a0w = Wa[o*3+0], a1w = Wa[o*3+1], a2w = Wa[o*3+2], bba = ba[o];
        const float inv = 1.0f / 256.0f;
        #pragma unroll
        for (int i = 0; i < 4; ++i) {
            const int h = 4 * ty + i;
            #pragma unroll
            for (int m = 0; m < 4; ++m) {
                float s0, s1, s2, s3;
                upk2(sacc[i][2*m],     s0, s1);
                upk2(sacc[i][2*m + 1], s2, s3);
                const float* pa = x2b + (size_t)(h0g + h) * HWD + 64*m + 4*tx;
                float4 a0 = *(const float4*)(pa);
                float4 a1 = *(const float4*)(pa + CH_STRIDE);
                float4 a2 = *(const float4*)(pa + 2*CH_STRIDE);
                float4 r;
                r.x = s0*inv + bba + a0w*a0.x + a1w*a1.x + a2w*a2.x;
                r.y = s1*inv + bba + a0w*a0.y + a1w*a1.y + a2w*a2.y;
                r.z = s2*inv + bba + a0w*a0.z + a1w*a1.z + a2w*a2.z;
                r.w = s3*inv + bba + a0w*a0.w + a1w*a1.w + a2w*a2.w;
                *(float4*)&bufA[h * ST_A + 64*m + 4*tx] = r;
            }
        }
    }
    __syncwarp();

    // ---------------- Softmax in place (warp per 8 rows; rows warp-private)
    {
        #pragma unroll 2
        for (int rr = 0; rr < 8; ++rr) {
            float* row = &bufA[(warpq * 8 + rr) * ST_A];
            float4 v0 = *(float4*)&row[lane * 4];
            float4 v1 = *(float4*)&row[128 + lane * 4];
            float m = fmaxf(fmaxf(fmaxf(v0.x, v0.y), fmaxf(v0.z, v0.w)),
                            fmaxf(fmaxf(v1.x, v1.y), fmaxf(v1.z, v1.w)));
            #pragma unroll
            for (int off = 16; off; off >>= 1)
                m = fmaxf(m, __shfl_xor_sync(0xffffffffu, m, off));
            v0.x = __expf(v0.x - m); v0.y = __expf(v0.y - m);
            v0.z = __expf(v0.z - m); v0.w = __expf(v0.w - m);
            v1.x = __expf(v1.x - m); v1.y = __expf(v1.y - m);
            v1.z = __expf(v1.z - m); v1.w = __expf(v1.w - m);
            float s = v0.x + v0.y + v0.z + v0.w + v1.x + v1.y + v1.z + v1.w;
            #pragma unroll
            for (int off = 16; off; off >>= 1)
                s += __shfl_xor_sync(0xffffffffu, s, off);
            const float rinv = 1.0f / s;
            v0.x *= rinv; v0.y *= rinv; v0.z *= rinv; v0.w *= rinv;
            v1.x *= rinv; v1.y *= rinv; v1.z *= rinv; v1.w *= rinv;
            *(float4*)&row[lane * 4] = v0;
            *(float4*)&row[128 + lane * 4] = v1;
        }
    }
    __syncwarp();   // P rows are read warp-privately in phase 3

    // ---------------- Phase 3: O = P V, 8 chunks of 32 g, double-buffered.
    // V chunk 0 already resides in buffer 0 (prefilled during phase-1 chunk 7).
    u64 oacc[4][8];
    #pragma unroll
    for (int i = 0; i < 4; ++i)
        #pragma unroll
        for (int m = 0; m < 8; ++m) oacc[i][m] = 0ull;

    for (int gt = 0; gt < 8; ++gt) {
        float* Bc = bufB + (gt & 1) * BUFB_FLOATS;
        float* Bn = bufB + ((gt & 1) ^ 1) * BUFB_FLOATS;
        const int pcol = gt * 32;

        for (int sub = 0; sub < 4; ++sub) {
            // ---- fill V slice for the NEXT chunk (overlaps this GEMM) ----
            if (gt < 7) {
                const int g = gv + sub;
                const float* p = x2b + (size_t)((gt + 1) * 32 + g) * HWD + wiv;
                float4 c0v = *(const float4*)(p);
                float4 c1v = *(const float4*)(p + CH_STRIDE);
                float4 c2v = *(const float4*)(p + 2 * CH_STRIDE);
                float4 r;
                r.x = bbv + v0w*c0v.x + v1w*c1v.x + v2w*c2v.x;
                r.y = bbv + v0w*c0v.y + v1w*c1v.y + v2w*c2v.y;
                r.z = bbv + v0w*c0v.z + v1w*c1v.z + v2w*c2v.z;
                r.w = bbv + v0w*c0v.w + v1w*c1v.w + v2w*c2v.w;
                *(float4*)&Bn[g * ST_B + wiv] = r;
            }

            // ---- GEMM: 8 g of current chunk ----
            #pragma unroll
            for (int dq = 0; dq < 2; ++dq) {
                const int g4 = sub * 8 + dq * 4;
                float4 pv[4];
                #pragma unroll
                for (int i = 0; i < 4; ++i)
                    pv[i] = *(const float4*)&bufA[(4*ty + i) * ST_A + pcol + g4];
                #pragma unroll
                for (int u = 0; u < 4; ++u) {
                    const float* vr = &Bc[(g4 + u) * ST_B + 4 * tx];
                    ulonglong2 V0 = *(const ulonglong2*)(vr);
                    ulonglong2 V1 = *(const ulonglong2*)(vr + 64);
                    ulonglong2 V2 = *(const ulonglong2*)(vr + 128);
                    ulonglong2 V3 = *(const ulonglong2*)(vr + 192);
                    #pragma unroll
                    for (int i = 0; i < 4; ++i) {
                        const float p = (&pv[i].x)[u];
                        u64 pp = pk2(p, p);
                        fma2(oacc[i][0], pp, V0.x); fma2(oacc[i][1], pp, V0.y);
                        fma2(oacc[i][2], pp, V1.x); fma2(oacc[i][3], pp, V1.y);
                        fma2(oacc[i][4], pp, V2.x); fma2(oacc[i][5], pp, V2.y);
                        fma2(oacc[i][6], pp, V3.x); fma2(oacc[i][7], pp, V3.y);
                    }
                }
            }
        }
        __syncthreads();
    }

    // ---------------- Output: [b][o][h][w], float4 coalesced
    float* ob = out + ((size_t)(b * 32 + o) * HWD + h0g) * HWD;
    #pragma unroll
    for (int i = 0; i < 4; ++i) {
        const int h = 4 * ty + i;
        #pragma unroll
        for (int m = 0; m < 4; ++m) {
            float4 r;
            upk2(oacc[i][2 * m],     r.x, r.y);
            upk2(oacc[i][2 * m + 1], r.z, r.w);
            *(float4*)&ob[(size_t)h * HWD + 64 * m + 4 * tx] = r;
        }
    }
}

extern "C" void kernel_launch(void* const* d_in, const int* in_sizes, int n_in,
                              void* d_out, int out_size)
{
    const float* x1 = (const float*)d_in[0];
    const float* x2 = (const float*)d_in[1];
    const float* Wq = (const float*)d_in[2];
    const float* bq = (const float*)d_in[3];
    const float* Wk = (const float*)d_in[4];
    const float* bk = (const float*)d_in[5];
    const float* Wv = (const float*)d_in[6];
    const float* bv = (const float*)d_in[7];
    const float* Wa = (const float*)d_in[8];
    const float* ba = (const float*)d_in[9];
    float* out = (float*)d_out;

    cudaFuncSetAttribute(fused_conv_attn_kernel,
                         cudaFuncAttributeMaxDynamicSharedMemorySize, SMEM_BYTES);

    dim3 grid(32, 2, 32);   // (o, h-block, b): consecutive CTAs share b -> x2[b] L2-resident
    fused_conv_attn_kernel<<<grid, THREADS, SMEM_BYTES>>>(
        x1, x2, Wq, bq, Wk, bk, Wv, bv, Wa, ba, out);
}